// round 6
// baseline (speedup 1.0000x reference)
#include <cuda_runtime.h>
#include <math.h>

#define NCH 8            // 2 batches x 4 classes
#define GD 96            // input spatial dim
#define PD 48            // pooled dim
#define PVOL (PD*PD*PD)  // 110592
#define ND 46            // base-voxel dim (48 - 2)
#define GSZ 64           // padded gram row stride (rows/cols 0..54 used)

#define BY 6             // spatial tile edge (y and z)
#define RXP 50           // padded raw tile x-extent
#define RY 8             // BY + 2
#define TILE (RY*RY*RXP) // 3200 floats per region (used part)
#define TILEP 3208       // region stride (bank decorrelation between regions)
#define OFF_ONES (4*TILEP)
#define SMEMF (5*TILEP)  // floats of dynamic smem

static __device__ float  g_la[NCH*PVOL];
static __device__ float  g_pr[NCH*PVOL];
static __device__ double g_gram[NCH*GSZ*GSZ];

// ---------------------------------------------------------------------------
__global__ void zero_kernel(float* out) {
    int i = blockIdx.x * blockDim.x + threadIdx.x;
    if (i < NCH*GSZ*GSZ) g_gram[i] = 0.0;
    if (i == 0) out[0] = 0.0f;
}

// ---------------------------------------------------------------------------
__global__ void pool_kernel(const float* __restrict__ logits,
                            const int* __restrict__ labels) {
    int idx = blockIdx.x * blockDim.x + threadIdx.x;
    if (idx >= NCH*PVOL) return;
    int ch  = idx / PVOL;
    int rem = idx - ch * PVOL;
    int p0 = rem / (PD*PD);
    int p1 = (rem / PD) % PD;
    int p2 = rem % PD;
    int n = ch >> 2;
    int c = ch & 3;

    const float* lg = logits + (size_t)ch * GD*GD*GD;
    const int*   lb = labels + (size_t)n  * GD*GD*GD;

    float la = 0.f, pr = 0.f;
    #pragma unroll
    for (int d0 = 0; d0 < 2; d0++) {
        #pragma unroll
        for (int d1 = 0; d1 < 2; d1++) {
            int base = ((2*p0 + d0) * GD + (2*p1 + d1)) * GD + 2*p2;
            float2 lv = *reinterpret_cast<const float2*>(lg + base);
            int2   bv = *reinterpret_cast<const int2*>(lb + base);
            {
                bool m = (bv.x < 4);
                if (m && bv.x == c) la = 1.f;
                float s = 1.f / (1.f + expf(-lv.x));
                float p = (m ? s : 0.f) + 1e-6f;
                pr = fmaxf(pr, p);
            }
            {
                bool m = (bv.y < 4);
                if (m && bv.y == c) la = 1.f;
                float s = 1.f / (1.f + expf(-lv.y));
                float p = (m ? s : 0.f) + 1e-6f;
                pr = fmaxf(pr, p);
            }
        }
    }
    g_la[idx] = la;
    g_pr[idx] = pr;
}

// ---------------------------------------------------------------------------
// Gram, triangular tile assignment. 7x7 grid of 8x8 tiles covers the 55x55
// lower triangle with 28 tiles. One block = 64 threads = 28 tiles of spatial
// tile A + 28 tiles of spatial tile B (same channel, adjacent y) + 8 dummies.
__device__ __forceinline__ int dof(int r, int laOff) {
    if (r < 27)  return laOff + ((r/9)*RY + (r/3)%3) * RXP + (r%3);
    if (r < 54) { int q = r - 27; return laOff + TILEP + ((q/9)*RY + (q/3)%3) * RXP + (q%3); }
    return OFF_ONES;   // rows/cols 54 (ones) and 55 (pad, never flushed)
}

__global__ __launch_bounds__(64) void gram_kernel() {
    extern __shared__ float s[];
    int ch  = blockIdx.y;
    int p   = blockIdx.x;          // spatial pair 0..31
    int sA  = 2*p;
    int syA = sA & 7, sz = sA >> 3;
    int y0A = syA*BY, y0B = y0A + BY, z0 = sz*BY;
    int tid = threadIdx.x;

    const float* la = g_la + (size_t)ch * PVOL;
    const float* pr = g_pr + (size_t)ch * PVOL;

    // load both spatial tiles (with halo) + ones region
    for (int i = tid; i < TILEP; i += 64) {
        float laA = 0.f, prA = 0.f, laB = 0.f, prB = 0.f;
        if (i < TILE) {
            int x = i % RXP;
            int t = i / RXP;
            int y = t % RY, z = t / RY;
            int gz = z0 + z;
            if (x < PD && gz < PD) {
                int gyA = y0A + y, gyB = y0B + y;
                if (gyA < PD) { int gi = (gz*PD + gyA)*PD + x; laA = la[gi]; prA = pr[gi]; }
                if (gyB < PD) { int gi = (gz*PD + gyB)*PD + x; laB = la[gi]; prB = pr[gi]; }
            }
        }
        s[i]           = laA;
        s[TILEP + i]   = prA;
        s[2*TILEP + i] = laB;
        s[3*TILEP + i] = prB;
        s[OFF_ONES + i] = 1.0f;
    }
    __syncthreads();

    // job: tid<28 -> tile A job tid; 28<=tid<56 -> tile B job tid-28; else dummy A job 0
    bool active = (tid < 56);
    bool isB = (tid >= 28) && (tid < 56);
    int j = active ? (isB ? tid - 28 : tid) : 0;
    int R = 0, jj = j;
    while (jj >= R + 1) { jj -= R + 1; R++; }
    int C = jj;                    // (R,C): lower-triangle tile, R>=C, R,C in [0,7)

    int laOff = isB ? 2*TILEP : 0;
    int myY0  = isB ? y0B : y0A;
    int myYC  = min(BY, ND - myY0);
    int zC    = min(BY, ND - z0);  // uniform across block (same sz)

    int rdel[8], cdel[8];
    #pragma unroll
    for (int i = 0; i < 8; i++) {
        rdel[i] = dof(R*8 + i, laOff);
        cdel[i] = dof(C*8 + i, laOff);
    }

    float acc[8][8];
    #pragma unroll
    for (int i = 0; i < 8; i++)
        #pragma unroll
        for (int q = 0; q < 8; q++) acc[i][q] = 0.f;

    for (int zb = 0; zb < zC; zb++) {
        for (int yb = 0; yb < BY; yb++) {
            if (yb >= myYC) continue;
            int kb = (zb*RY + yb) * RXP;
            #pragma unroll 2
            for (int xb = 0; xb < ND; xb++) {
                int k = kb + xb;
                float a[8], b[8];
                #pragma unroll
                for (int i = 0; i < 8; i++) a[i] = s[rdel[i] + k];
                #pragma unroll
                for (int q = 0; q < 8; q++) b[q] = s[cdel[q] + k];
                #pragma unroll
                for (int i = 0; i < 8; i++)
                    #pragma unroll
                    for (int q = 0; q < 8; q++)
                        acc[i][q] = fmaf(a[i], b[q], acc[i][q]);
            }
        }
    }

    if (active) {
        double* G = g_gram + (size_t)ch * GSZ * GSZ;
        #pragma unroll
        for (int i = 0; i < 8; i++) {
            int r = R*8 + i;
            if (r > 54) continue;
            #pragma unroll
            for (int q = 0; q < 8; q++) {
                int c = C*8 + q;
                if (c > 54) continue;
                if (R == C && q > i) continue;   // diag tile: lower half only
                atomicAdd(&G[r*GSZ + c], (double)acc[i][q]);
            }
        }
    }
}

// ---------------------------------------------------------------------------
// Finalize: one warp per channel, warp-synchronous LDL^T. Same math as the
// validated block version, __syncwarp instead of block barriers.
__device__ __forceinline__ double G2(const double* G, int a, int b) {
    return (a >= b) ? G[a*GSZ + b] : G[b*GSZ + a];
}

__device__ void ldl27w(double* A, double* invD, int tid) {
    for (int k = 0; k < 27; k++) {
        double iv = 1.0 / A[k*27 + k];   // redundant per lane, no serialization
        if (tid == 0) invD[k] = iv;
        for (int e = tid; e < 27*27; e += 32) {
            int i = e / 27, q = e % 27;
            if (q > k && q <= i)
                A[e] -= A[i*27 + k] * A[q*27 + k] * iv;
        }
        __syncwarp();
    }
}

__global__ __launch_bounds__(32) void finalize_kernel(float* out) {
    __shared__ double Cla[27*27], P[27*27], U[27*27];
    __shared__ double invD[27];
    __shared__ double red;
    int ch = blockIdx.x;
    int tid = threadIdx.x;
    const double* G = g_gram + (size_t)ch * GSZ * GSZ;
    const double M = (double)(ND*ND*ND);   // 97336
    const double ALPHA = 0.0005;

    if (tid == 0) red = 0.0;

    for (int e = tid; e < 27*27; e += 32) {
        int i = e / 27, q = e % 27;
        double Sli = G[54*GSZ + i];
        double Slj = G[54*GSZ + q];
        double Spi = G[54*GSZ + 27 + i];
        double Spj = G[54*GSZ + 27 + q];
        Cla[e] = G2(G, i, q)          - Sli*Slj / M;
        P[e]   = G2(G, 27+i, 27+q)    - Spi*Spj / M + (i == q ? ALPHA : 0.0);
        U[e]   = G[(27+i)*GSZ + q]    - Slj*Spi / M;   // cov(la_q, pr_i), lower read
    }
    __syncwarp();

    ldl27w(P, invD, tid);   // P = L1 D L1^T (unscaled lower), invD = 1/D_k

    // U <- L1^{-1} U
    for (int k = 0; k < 27; k++) {
        double iv = invD[k];
        for (int e = tid; e < (26 - k) * 27; e += 32) {
            int i = k + 1 + e / 27;
            int m = e % 27;
            U[i*27 + m] -= P[i*27 + k] * iv * U[k*27 + m];
        }
        __syncwarp();
    }

    // appro (lower) = la_cov - U^T D^{-1} U + aI -> P
    for (int e = tid; e < 27*27; e += 32) {
        int i = e / 27, q = e % 27;
        if (q > i) continue;
        double v = Cla[e];
        #pragma unroll 9
        for (int k = 0; k < 27; k++)
            v -= invD[k] * U[k*27 + i] * U[k*27 + q];
        P[e] = v + (i == q ? ALPHA : 0.0);
    }
    __syncwarp();

    ldl27w(P, invD, tid);   // diag now holds D2_k; chol diag = sqrt(D2_k)

    if (tid < 27) atomicAdd(&red, log(sqrt(P[tid*27 + tid]) + 1e-8));
    __syncwarp();
    if (tid == 0) atomicAdd(out, (float)(red / 54.0));
}

// ---------------------------------------------------------------------------
extern "C" void kernel_launch(void* const* d_in, const int* in_sizes, int n_in,
                              void* d_out, int out_size) {
    const float* logits = (const float*)d_in[0];
    const int*   labels = (const int*)d_in[1];
    float* out = (float*)d_out;

    static bool attr_set = false;
    if (!attr_set) {
        cudaFuncSetAttribute(gram_kernel,
                             cudaFuncAttributeMaxDynamicSharedMemorySize,
                             SMEMF * (int)sizeof(float));
        attr_set = true;
    }

    zero_kernel<<<(NCH*GSZ*GSZ + 255)/256, 256>>>(out);
    pool_kernel<<<(NCH*PVOL + 255)/256, 256>>>(logits, labels);
    dim3 g(32, NCH);   // 32 spatial pairs x 8 channels = 256 blocks
    gram_kernel<<<g, 64, SMEMF * sizeof(float)>>>();
    finalize_kernel<<<NCH, 32>>>(out);
}

// round 7
// speedup vs baseline: 1.4198x; 1.4198x over previous
#include <cuda_runtime.h>
#include <math.h>

#define NCH 8            // 2 batches x 4 classes
#define GD 96            // input spatial dim
#define PD 48            // pooled dim
#define PVOL (PD*PD*PD)  // 110592
#define ND 46            // base-voxel dim (48 - 2)
#define GSZ 64           // padded gram row stride (rows/cols 0..54 used)

#define BY 6             // spatial tile edge (y and z)
#define RXP 50           // padded raw tile x-extent
#define RY 8             // BY + 2
#define TILE (RY*RY*RXP) // 3200 floats per region (used part)
#define TILEP 3208       // region stride (bank decorrelation between regions)
#define OFF_ONES (4*TILEP)
#define SMEMF (5*TILEP)  // floats of dynamic smem

#define FT 128           // finalize threads
#define BSZ 54           // big matrix size

static __device__ float  g_la[NCH*PVOL];
static __device__ float  g_pr[NCH*PVOL];
static __device__ double g_gram[NCH*GSZ*GSZ];

// ---------------------------------------------------------------------------
__global__ void zero_kernel(float* out) {
    int i = blockIdx.x * blockDim.x + threadIdx.x;
    if (i < NCH*GSZ*GSZ) g_gram[i] = 0.0;
    if (i == 0) out[0] = 0.0f;
}

// ---------------------------------------------------------------------------
__global__ void pool_kernel(const float* __restrict__ logits,
                            const int* __restrict__ labels) {
    int idx = blockIdx.x * blockDim.x + threadIdx.x;
    if (idx >= NCH*PVOL) return;
    int ch  = idx / PVOL;
    int rem = idx - ch * PVOL;
    int p0 = rem / (PD*PD);
    int p1 = (rem / PD) % PD;
    int p2 = rem % PD;
    int n = ch >> 2;
    int c = ch & 3;

    const float* lg = logits + (size_t)ch * GD*GD*GD;
    const int*   lb = labels + (size_t)n  * GD*GD*GD;

    float la = 0.f, pr = 0.f;
    #pragma unroll
    for (int d0 = 0; d0 < 2; d0++) {
        #pragma unroll
        for (int d1 = 0; d1 < 2; d1++) {
            int base = ((2*p0 + d0) * GD + (2*p1 + d1)) * GD + 2*p2;
            float2 lv = *reinterpret_cast<const float2*>(lg + base);
            int2   bv = *reinterpret_cast<const int2*>(lb + base);
            {
                bool m = (bv.x < 4);
                if (m && bv.x == c) la = 1.f;
                float s = 1.f / (1.f + expf(-lv.x));
                float p = (m ? s : 0.f) + 1e-6f;
                pr = fmaxf(pr, p);
            }
            {
                bool m = (bv.y < 4);
                if (m && bv.y == c) la = 1.f;
                float s = 1.f / (1.f + expf(-lv.y));
                float p = (m ? s : 0.f) + 1e-6f;
                pr = fmaxf(pr, p);
            }
        }
    }
    g_la[idx] = la;
    g_pr[idx] = pr;
}

// ---------------------------------------------------------------------------
// Gram, triangular tile assignment (validated R5). 7x7 grid of 8x8 tiles
// covers the 55x55 lower triangle with 28 tiles; one block = two spatial
// tiles (A,B) x 28 jobs + 8 dummies.
__device__ __forceinline__ int dof(int r, int laOff) {
    if (r < 27)  return laOff + ((r/9)*RY + (r/3)%3) * RXP + (r%3);
    if (r < 54) { int q = r - 27; return laOff + TILEP + ((q/9)*RY + (q/3)%3) * RXP + (q%3); }
    return OFF_ONES;
}

__global__ __launch_bounds__(64) void gram_kernel() {
    extern __shared__ float s[];
    int ch  = blockIdx.y;
    int p   = blockIdx.x;          // spatial pair 0..31
    int sA  = 2*p;
    int syA = sA & 7, sz = sA >> 3;
    int y0A = syA*BY, y0B = y0A + BY, z0 = sz*BY;
    int tid = threadIdx.x;

    const float* la = g_la + (size_t)ch * PVOL;
    const float* pr = g_pr + (size_t)ch * PVOL;

    for (int i = tid; i < TILEP; i += 64) {
        float laA = 0.f, prA = 0.f, laB = 0.f, prB = 0.f;
        if (i < TILE) {
            int x = i % RXP;
            int t = i / RXP;
            int y = t % RY, z = t / RY;
            int gz = z0 + z;
            if (x < PD && gz < PD) {
                int gyA = y0A + y, gyB = y0B + y;
                if (gyA < PD) { int gi = (gz*PD + gyA)*PD + x; laA = la[gi]; prA = pr[gi]; }
                if (gyB < PD) { int gi = (gz*PD + gyB)*PD + x; laB = la[gi]; prB = pr[gi]; }
            }
        }
        s[i]           = laA;
        s[TILEP + i]   = prA;
        s[2*TILEP + i] = laB;
        s[3*TILEP + i] = prB;
        s[OFF_ONES + i] = 1.0f;
    }
    __syncthreads();

    bool active = (tid < 56);
    bool isB = (tid >= 28) && (tid < 56);
    int j = active ? (isB ? tid - 28 : tid) : 0;
    int R = 0, jj = j;
    while (jj >= R + 1) { jj -= R + 1; R++; }
    int C = jj;

    int laOff = isB ? 2*TILEP : 0;
    int myY0  = isB ? y0B : y0A;
    int myYC  = min(BY, ND - myY0);
    int zC    = min(BY, ND - z0);

    int rdel[8], cdel[8];
    #pragma unroll
    for (int i = 0; i < 8; i++) {
        rdel[i] = dof(R*8 + i, laOff);
        cdel[i] = dof(C*8 + i, laOff);
    }

    float acc[8][8];
    #pragma unroll
    for (int i = 0; i < 8; i++)
        #pragma unroll
        for (int q = 0; q < 8; q++) acc[i][q] = 0.f;

    for (int zb = 0; zb < zC; zb++) {
        for (int yb = 0; yb < BY; yb++) {
            if (yb >= myYC) continue;
            int kb = (zb*RY + yb) * RXP;
            #pragma unroll 2
            for (int xb = 0; xb < ND; xb++) {
                int k = kb + xb;
                float a[8], b[8];
                #pragma unroll
                for (int i = 0; i < 8; i++) a[i] = s[rdel[i] + k];
                #pragma unroll
                for (int q = 0; q < 8; q++) b[q] = s[cdel[q] + k];
                #pragma unroll
                for (int i = 0; i < 8; i++)
                    #pragma unroll
                    for (int q = 0; q < 8; q++)
                        acc[i][q] = fmaf(a[i], b[q], acc[i][q]);
            }
        }
    }

    if (active) {
        double* G = g_gram + (size_t)ch * GSZ * GSZ;
        #pragma unroll
        for (int i = 0; i < 8; i++) {
            int r = R*8 + i;
            if (r > 54) continue;
            #pragma unroll
            for (int q = 0; q < 8; q++) {
                int c = C*8 + q;
                if (c > 54) continue;
                if (R == C && q > i) continue;
                atomicAdd(&G[r*GSZ + c], (double)acc[i][q]);
            }
        }
    }
}

// ---------------------------------------------------------------------------
// Finalize via Schur-determinant identity:
//   rmi_ch = sum_{k=27}^{53} 0.5*log(D_k)  of the LDL^T of
//   BIG = [[pr_cov+aI, X^T],[X, la_cov+aI]]   (54x54, lower triangle only).
// One barrier per step; reciprocal via fp32 seed + 2 fp64 Newton steps
// computed redundantly in every lane (no DDIV, no broadcast barrier).
__device__ __forceinline__ double drcp(double x) {
    double iv = (double)__fdividef(1.0f, (float)x);
    iv = __fma_rn(__fma_rn(-x, iv, 1.0), iv, iv);
    iv = __fma_rn(__fma_rn(-x, iv, 1.0), iv, iv);
    return iv;
}

__global__ __launch_bounds__(FT) void finalize_kernel(float* out) {
    __shared__ double A[BSZ*BSZ];
    __shared__ double red;
    int ch = blockIdx.x;
    int tid = threadIdx.x;
    const double* G = g_gram + (size_t)ch * GSZ * GSZ;
    const double invM = 1.0 / (double)(ND*ND*ND);   // 1/97336
    const double ALPHA = 0.0005;

    if (tid == 0) red = 0.0;

    // Fill lower triangle of BIG. Index a<27 -> pr_a (gram row 27+a),
    // a>=27 -> la_{a-27} (gram row a-27). Gram is stored lower-triangular.
    for (int e = tid; e < BSZ*BSZ; e += FT) {
        int a = e / BSZ, b = e % BSZ;
        if (b > a) continue;
        double v;
        if (a < 27) {               // b <= a < 27 : pr-pr
            double Spa = G[54*GSZ + 27 + a], Spb = G[54*GSZ + 27 + b];
            v = G[(27+a)*GSZ + (27+b)] - Spa*Spb*invM + (a == b ? ALPHA : 0.0);
        } else if (b < 27) {        // la_{a-27} x pr_b : gram[(27+b)][a-27]
            int i = a - 27;
            double Sli = G[54*GSZ + i], Spb = G[54*GSZ + 27 + b];
            v = G[(27+b)*GSZ + i] - Sli*Spb*invM;
        } else {                    // la-la
            int i = a - 27, q = b - 27;   // i >= q
            double Sli = G[54*GSZ + i], Slq = G[54*GSZ + q];
            v = G[i*GSZ + q] - Sli*Slq*invM + (i == q ? ALPHA : 0.0);
        }
        A[e] = v;
    }
    __syncthreads();

    // LDL^T, unscaled-column form: A[i][j] -= A[i][k]*A[j][k]/D_k
    for (int k = 0; k < BSZ - 1; k++) {
        double iv = drcp(A[k*BSZ + k]);   // redundant per lane
        for (int e = tid; e < BSZ*BSZ; e += FT) {
            int i = e / BSZ, q = e % BSZ;
            if (q > k && q <= i)
                A[e] -= A[i*BSZ + k] * A[q*BSZ + k] * iv;
        }
        __syncthreads();
    }

    // rmi = sum over trailing 27 pivots of log(sqrt(D_k) + 1e-8)
    if (tid >= 27 && tid < 54) {
        int k = tid;
        atomicAdd(&red, log(sqrt(A[k*BSZ + k]) + 1e-8));
    }
    __syncthreads();
    if (tid == 0) atomicAdd(out, (float)(red / 54.0));
}

// ---------------------------------------------------------------------------
extern "C" void kernel_launch(void* const* d_in, const int* in_sizes, int n_in,
                              void* d_out, int out_size) {
    const float* logits = (const float*)d_in[0];
    const int*   labels = (const int*)d_in[1];
    float* out = (float*)d_out;

    cudaFuncSetAttribute(gram_kernel,
                         cudaFuncAttributeMaxDynamicSharedMemorySize,
                         SMEMF * (int)sizeof(float));

    zero_kernel<<<(NCH*GSZ*GSZ + 255)/256, 256>>>(out);
    pool_kernel<<<(NCH*PVOL + 255)/256, 256>>>(logits, labels);
    dim3 g(32, NCH);   // 32 spatial pairs x 8 channels = 256 blocks
    gram_kernel<<<g, 64, SMEMF * sizeof(float)>>>();
    finalize_kernel<<<NCH, FT>>>(out);
}

// round 8
// speedup vs baseline: 1.4862x; 1.0467x over previous
#include <cuda_runtime.h>
#include <math.h>

#define NCH 8            // 2 batches x 4 classes
#define GD 96            // input spatial dim
#define PD 48            // pooled dim
#define PVOL (PD*PD*PD)  // 110592
#define ND 46            // base-voxel dim (48 - 2)
#define GSZ 64           // padded gram row stride (rows/cols 0..54 used)

#define BY 6             // spatial tile edge (y and z)
#define RXP 50           // padded raw tile x-extent
#define RY 8             // BY + 2
#define TILE (RY*RY*RXP) // 3200 floats per region (used part)
#define TILEP 3208       // region stride (bank decorrelation between regions)
#define OFF_ONES (4*TILEP)
#define SMEMF (5*TILEP)  // floats of dynamic smem

#define FT 128           // finalize threads
#define BSZ 55           // big matrix size (dummy row 0 + 27 pr + 27 la)
#define NTRI (BSZ*(BSZ+1)/2)   // 1540 lower-tri elements
#define NPER 13                // ceil(1540/128)

static __device__ float  g_la[NCH*PVOL];
static __device__ float  g_pr[NCH*PVOL];
static __device__ double g_gram[NCH*GSZ*GSZ];

// ---------------------------------------------------------------------------
__global__ void zero_kernel(float* out) {
    int i = blockIdx.x * blockDim.x + threadIdx.x;
    if (i < NCH*GSZ*GSZ) g_gram[i] = 0.0;
    if (i == 0) out[0] = 0.0f;
}

// ---------------------------------------------------------------------------
__global__ void pool_kernel(const float* __restrict__ logits,
                            const int* __restrict__ labels) {
    int idx = blockIdx.x * blockDim.x + threadIdx.x;
    if (idx >= NCH*PVOL) return;
    int ch  = idx / PVOL;
    int rem = idx - ch * PVOL;
    int p0 = rem / (PD*PD);
    int p1 = (rem / PD) % PD;
    int p2 = rem % PD;
    int n = ch >> 2;
    int c = ch & 3;

    const float* lg = logits + (size_t)ch * GD*GD*GD;
    const int*   lb = labels + (size_t)n  * GD*GD*GD;

    float la = 0.f, pr = 0.f;
    #pragma unroll
    for (int d0 = 0; d0 < 2; d0++) {
        #pragma unroll
        for (int d1 = 0; d1 < 2; d1++) {
            int base = ((2*p0 + d0) * GD + (2*p1 + d1)) * GD + 2*p2;
            float2 lv = *reinterpret_cast<const float2*>(lg + base);
            int2   bv = *reinterpret_cast<const int2*>(lb + base);
            {
                bool m = (bv.x < 4);
                if (m && bv.x == c) la = 1.f;
                float s = 1.f / (1.f + expf(-lv.x));
                float p = (m ? s : 0.f) + 1e-6f;
                pr = fmaxf(pr, p);
            }
            {
                bool m = (bv.y < 4);
                if (m && bv.y == c) la = 1.f;
                float s = 1.f / (1.f + expf(-lv.y));
                float p = (m ? s : 0.f) + 1e-6f;
                pr = fmaxf(pr, p);
            }
        }
    }
    g_la[idx] = la;
    g_pr[idx] = pr;
}

// ---------------------------------------------------------------------------
// Gram (validated R5/R6): triangular 7x7 tile grid, two spatial tiles/block.
__device__ __forceinline__ int dof(int r, int laOff) {
    if (r < 27)  return laOff + ((r/9)*RY + (r/3)%3) * RXP + (r%3);
    if (r < 54) { int q = r - 27; return laOff + TILEP + ((q/9)*RY + (q/3)%3) * RXP + (q%3); }
    return OFF_ONES;
}

__global__ __launch_bounds__(64) void gram_kernel() {
    extern __shared__ float s[];
    int ch  = blockIdx.y;
    int p   = blockIdx.x;
    int sA  = 2*p;
    int syA = sA & 7, sz = sA >> 3;
    int y0A = syA*BY, y0B = y0A + BY, z0 = sz*BY;
    int tid = threadIdx.x;

    const float* la = g_la + (size_t)ch * PVOL;
    const float* pr = g_pr + (size_t)ch * PVOL;

    for (int i = tid; i < TILEP; i += 64) {
        float laA = 0.f, prA = 0.f, laB = 0.f, prB = 0.f;
        if (i < TILE) {
            int x = i % RXP;
            int t = i / RXP;
            int y = t % RY, z = t / RY;
            int gz = z0 + z;
            if (x < PD && gz < PD) {
                int gyA = y0A + y, gyB = y0B + y;
                if (gyA < PD) { int gi = (gz*PD + gyA)*PD + x; laA = la[gi]; prA = pr[gi]; }
                if (gyB < PD) { int gi = (gz*PD + gyB)*PD + x; laB = la[gi]; prB = pr[gi]; }
            }
        }
        s[i]           = laA;
        s[TILEP + i]   = prA;
        s[2*TILEP + i] = laB;
        s[3*TILEP + i] = prB;
        s[OFF_ONES + i] = 1.0f;
    }
    __syncthreads();

    bool active = (tid < 56);
    bool isB = (tid >= 28) && (tid < 56);
    int j = active ? (isB ? tid - 28 : tid) : 0;
    int R = 0, jj = j;
    while (jj >= R + 1) { jj -= R + 1; R++; }
    int C = jj;

    int laOff = isB ? 2*TILEP : 0;
    int myY0  = isB ? y0B : y0A;
    int myYC  = min(BY, ND - myY0);
    int zC    = min(BY, ND - z0);

    int rdel[8], cdel[8];
    #pragma unroll
    for (int i = 0; i < 8; i++) {
        rdel[i] = dof(R*8 + i, laOff);
        cdel[i] = dof(C*8 + i, laOff);
    }

    float acc[8][8];
    #pragma unroll
    for (int i = 0; i < 8; i++)
        #pragma unroll
        for (int q = 0; q < 8; q++) acc[i][q] = 0.f;

    for (int zb = 0; zb < zC; zb++) {
        for (int yb = 0; yb < BY; yb++) {
            if (yb >= myYC) continue;
            int kb = (zb*RY + yb) * RXP;
            #pragma unroll 2
            for (int xb = 0; xb < ND; xb++) {
                int k = kb + xb;
                float a[8], b[8];
                #pragma unroll
                for (int i = 0; i < 8; i++) a[i] = s[rdel[i] + k];
                #pragma unroll
                for (int q = 0; q < 8; q++) b[q] = s[cdel[q] + k];
                #pragma unroll
                for (int i = 0; i < 8; i++)
                    #pragma unroll
                    for (int q = 0; q < 8; q++)
                        acc[i][q] = fmaf(a[i], b[q], acc[i][q]);
            }
        }
    }

    if (active) {
        double* G = g_gram + (size_t)ch * GSZ * GSZ;
        #pragma unroll
        for (int i = 0; i < 8; i++) {
            int r = R*8 + i;
            if (r > 54) continue;
            #pragma unroll
            for (int q = 0; q < 8; q++) {
                int c = C*8 + q;
                if (c > 54) continue;
                if (R == C && q > i) continue;
                atomicAdd(&G[r*GSZ + c], (double)acc[i][q]);
            }
        }
    }
}

// ---------------------------------------------------------------------------
// Finalize: Schur-determinant LDL^T with rank-2 block pivots on the 55x55
// bordered matrix [[1,0],[0,BIG]], BIG = [[pr_cov+aI, X^T],[X, la_cov+aI]].
// rmi = 0.5 * (sum_{j=14..26} log det(B_j) + log D_54).
// Owner-computes: each thread keeps ~12 lower-tri accumulators in registers.
__device__ __forceinline__ double drcp(double x) {
    double iv = (double)__fdividef(1.0f, (float)x);
    iv = __fma_rn(__fma_rn(-x, iv, 1.0), iv, iv);
    iv = __fma_rn(__fma_rn(-x, iv, 1.0), iv, iv);
    return iv;
}

__global__ __launch_bounds__(FT) void finalize_kernel(float* out) {
    __shared__ double A[BSZ*BSZ];
    int ch = blockIdx.x;
    int tid = threadIdx.x;
    const double* G = g_gram + (size_t)ch * GSZ * GSZ;
    const double invM = 1.0 / (double)(ND*ND*ND);   // 1/97336
    const double ALPHA = 0.0005;

    // Fill lower triangle. Index map: 0 = dummy (unit pivot),
    // 1..27 -> pr_{a-1} (gram row 26+a), 28..54 -> la_{a-28} (gram row a-28).
    for (int e = tid; e < BSZ*BSZ; e += FT) {
        int a = e / BSZ, b = e % BSZ;
        if (b > a) continue;
        double v;
        if (b == 0) {
            v = (a == 0) ? 1.0 : 0.0;
        } else if (a <= 27) {               // pr-pr
            double Spa = G[54*GSZ + 26 + a], Spb = G[54*GSZ + 26 + b];
            v = G[(26+a)*GSZ + (26+b)] - Spa*Spb*invM + (a == b ? ALPHA : 0.0);
        } else if (b <= 27) {               // la_{a-28} x pr_{b-1}
            int i = a - 28;
            double Sli = G[54*GSZ + i], Spb = G[54*GSZ + 26 + b];
            v = G[(26+b)*GSZ + i] - Sli*Spb*invM;
        } else {                            // la-la
            int i = a - 28, q = b - 28;     // i >= q
            double Sli = G[54*GSZ + i], Slq = G[54*GSZ + q];
            v = G[i*GSZ + q] - Sli*Slq*invM + (i == q ? ALPHA : 0.0);
        }
        A[e] = v;
    }
    __syncthreads();

    // fixed owner assignment of lower-triangle elements
    int iB[NPER], qB[NPER], qV[NPER];
    double accv[NPER];
    #pragma unroll
    for (int n = 0; n < NPER; n++) {
        int t = tid + n*FT;
        if (t < NTRI) {
            int i = (int)((sqrtf(8.0f*(float)t + 1.0f) - 1.0f) * 0.5f);
            while ((i+1)*(i+2)/2 <= t) i++;
            while (i*(i+1)/2 > t) i--;
            int q = t - i*(i+1)/2;
            iB[n] = i*BSZ; qB[n] = q*BSZ; qV[n] = q;
            accv[n] = A[i*BSZ + q];
        } else {
            iB[n] = 0; qB[n] = 0; qV[n] = -1; accv[n] = 0.0;
        }
    }

    double logsum = 0.0;
    for (int j = 0; j < 27; j++) {
        int k0 = 2*j, k1 = k0 + 1;
        double a = A[k0*BSZ + k0];
        double b = A[k1*BSZ + k0];
        double c = A[k1*BSZ + k1];
        double det = a*c - b*b;
        double idet = drcp(det);
        double i00 =  c*idet, i01 = -b*idet, i11 = a*idet;
        if (tid == 0 && j >= 14) logsum += log(det);
        #pragma unroll
        for (int n = 0; n < NPER; n++) {
            if (qV[n] >= k0 + 2) {
                double wi0 = A[iB[n] + k0], wi1 = A[iB[n] + k1];
                double wq0 = A[qB[n] + k0], wq1 = A[qB[n] + k1];
                double t0 = i00*wq0 + i01*wq1;
                double t1 = i01*wq0 + i11*wq1;
                accv[n] -= wi0*t0 + wi1*t1;
                A[iB[n] + qV[n]] = accv[n];
            }
        }
        __syncthreads();
    }

    if (tid == 0) {
        double d54 = A[54*BSZ + 54];
        double rmi = 0.5 * (logsum + log(d54));
        atomicAdd(out, (float)(rmi / 54.0));
    }
}

// ---------------------------------------------------------------------------
extern "C" void kernel_launch(void* const* d_in, const int* in_sizes, int n_in,
                              void* d_out, int out_size) {
    const float* logits = (const float*)d_in[0];
    const int*   labels = (const int*)d_in[1];
    float* out = (float*)d_out;

    cudaFuncSetAttribute(gram_kernel,
                         cudaFuncAttributeMaxDynamicSharedMemorySize,
                         SMEMF * (int)sizeof(float));

    zero_kernel<<<(NCH*GSZ*GSZ + 255)/256, 256>>>(out);
    pool_kernel<<<(NCH*PVOL + 255)/256, 256>>>(logits, labels);
    dim3 g(32, NCH);   // 32 spatial pairs x 8 channels = 256 blocks
    gram_kernel<<<g, 64, SMEMF * sizeof(float)>>>();
    finalize_kernel<<<NCH, FT>>>(out);
}

// round 9
// speedup vs baseline: 1.8231x; 1.2267x over previous
#include <cuda_runtime.h>
#include <math.h>

#define NCH 8            // 2 batches x 4 classes
#define GD 96            // input spatial dim
#define PD 48            // pooled dim
#define PVOL (PD*PD*PD)  // 110592
#define ND 46            // base-voxel dim (48 - 2)
#define GSZ 64           // padded gram row stride (rows/cols 0..54 used)

#define BY 6             // spatial tile edge (y and z)
#define RXP 50           // padded raw tile x-extent
#define RY 8             // BY + 2
#define TILE (RY*RY*RXP) // 3200 floats per region (used part)
#define TILEP 3208       // region stride (bank decorrelation between regions)
#define OFF_ONES (4*TILEP)
#define SMEMF (5*TILEP)  // floats of dynamic smem

#define FT 128           // finalize threads
#define BSZ 54           // big matrix size
#define NTRI (BSZ*(BSZ+1)/2)   // 1485 lower-tri elements
#define NPER 12                // ceil(1485/128)

static __device__ float  g_la[NCH*PVOL];
static __device__ float  g_pr[NCH*PVOL];
static __device__ double g_gram[NCH*GSZ*GSZ];

// ---------------------------------------------------------------------------
__global__ void zero_kernel(float* out) {
    int i = blockIdx.x * blockDim.x + threadIdx.x;
    if (i < NCH*GSZ*GSZ) g_gram[i] = 0.0;
    if (i == 0) out[0] = 0.0f;
}

// ---------------------------------------------------------------------------
__global__ void pool_kernel(const float* __restrict__ logits,
                            const int* __restrict__ labels) {
    int idx = blockIdx.x * blockDim.x + threadIdx.x;
    if (idx >= NCH*PVOL) return;
    int ch  = idx / PVOL;
    int rem = idx - ch * PVOL;
    int p0 = rem / (PD*PD);
    int p1 = (rem / PD) % PD;
    int p2 = rem % PD;
    int n = ch >> 2;
    int c = ch & 3;

    const float* lg = logits + (size_t)ch * GD*GD*GD;
    const int*   lb = labels + (size_t)n  * GD*GD*GD;

    float la = 0.f, pr = 0.f;
    #pragma unroll
    for (int d0 = 0; d0 < 2; d0++) {
        #pragma unroll
        for (int d1 = 0; d1 < 2; d1++) {
            int base = ((2*p0 + d0) * GD + (2*p1 + d1)) * GD + 2*p2;
            float2 lv = *reinterpret_cast<const float2*>(lg + base);
            int2   bv = *reinterpret_cast<const int2*>(lb + base);
            {
                bool m = (bv.x < 4);
                if (m && bv.x == c) la = 1.f;
                float s = 1.f / (1.f + expf(-lv.x));
                float p = (m ? s : 0.f) + 1e-6f;
                pr = fmaxf(pr, p);
            }
            {
                bool m = (bv.y < 4);
                if (m && bv.y == c) la = 1.f;
                float s = 1.f / (1.f + expf(-lv.y));
                float p = (m ? s : 0.f) + 1e-6f;
                pr = fmaxf(pr, p);
            }
        }
    }
    g_la[idx] = la;
    g_pr[idx] = pr;
}

// ---------------------------------------------------------------------------
// Gram (validated R5-R7): triangular 7x7 tile grid, two spatial tiles/block.
__device__ __forceinline__ int dof(int r, int laOff) {
    if (r < 27)  return laOff + ((r/9)*RY + (r/3)%3) * RXP + (r%3);
    if (r < 54) { int q = r - 27; return laOff + TILEP + ((q/9)*RY + (q/3)%3) * RXP + (q%3); }
    return OFF_ONES;
}

__global__ __launch_bounds__(64) void gram_kernel() {
    extern __shared__ float s[];
    int ch  = blockIdx.y;
    int p   = blockIdx.x;
    int sA  = 2*p;
    int syA = sA & 7, sz = sA >> 3;
    int y0A = syA*BY, y0B = y0A + BY, z0 = sz*BY;
    int tid = threadIdx.x;

    const float* la = g_la + (size_t)ch * PVOL;
    const float* pr = g_pr + (size_t)ch * PVOL;

    for (int i = tid; i < TILEP; i += 64) {
        float laA = 0.f, prA = 0.f, laB = 0.f, prB = 0.f;
        if (i < TILE) {
            int x = i % RXP;
            int t = i / RXP;
            int y = t % RY, z = t / RY;
            int gz = z0 + z;
            if (x < PD && gz < PD) {
                int gyA = y0A + y, gyB = y0B + y;
                if (gyA < PD) { int gi = (gz*PD + gyA)*PD + x; laA = la[gi]; prA = pr[gi]; }
                if (gyB < PD) { int gi = (gz*PD + gyB)*PD + x; laB = la[gi]; prB = pr[gi]; }
            }
        }
        s[i]           = laA;
        s[TILEP + i]   = prA;
        s[2*TILEP + i] = laB;
        s[3*TILEP + i] = prB;
        s[OFF_ONES + i] = 1.0f;
    }
    __syncthreads();

    bool active = (tid < 56);
    bool isB = (tid >= 28) && (tid < 56);
    int j = active ? (isB ? tid - 28 : tid) : 0;
    int R = 0, jj = j;
    while (jj >= R + 1) { jj -= R + 1; R++; }
    int C = jj;

    int laOff = isB ? 2*TILEP : 0;
    int myY0  = isB ? y0B : y0A;
    int myYC  = min(BY, ND - myY0);
    int zC    = min(BY, ND - z0);

    int rdel[8], cdel[8];
    #pragma unroll
    for (int i = 0; i < 8; i++) {
        rdel[i] = dof(R*8 + i, laOff);
        cdel[i] = dof(C*8 + i, laOff);
    }

    float acc[8][8];
    #pragma unroll
    for (int i = 0; i < 8; i++)
        #pragma unroll
        for (int q = 0; q < 8; q++) acc[i][q] = 0.f;

    for (int zb = 0; zb < zC; zb++) {
        for (int yb = 0; yb < BY; yb++) {
            if (yb >= myYC) continue;
            int kb = (zb*RY + yb) * RXP;
            #pragma unroll 2
            for (int xb = 0; xb < ND; xb++) {
                int k = kb + xb;
                float a[8], b[8];
                #pragma unroll
                for (int i = 0; i < 8; i++) a[i] = s[rdel[i] + k];
                #pragma unroll
                for (int q = 0; q < 8; q++) b[q] = s[cdel[q] + k];
                #pragma unroll
                for (int i = 0; i < 8; i++)
                    #pragma unroll
                    for (int q = 0; q < 8; q++)
                        acc[i][q] = fmaf(a[i], b[q], acc[i][q]);
            }
        }
    }

    if (active) {
        double* G = g_gram + (size_t)ch * GSZ * GSZ;
        #pragma unroll
        for (int i = 0; i < 8; i++) {
            int r = R*8 + i;
            if (r > 54) continue;
            #pragma unroll
            for (int q = 0; q < 8; q++) {
                int c = C*8 + q;
                if (c > 54) continue;
                if (R == C && q > i) continue;
                atomicAdd(&G[r*GSZ + c], (double)acc[i][q]);
            }
        }
    }
}

// ---------------------------------------------------------------------------
// double-float (df64) arithmetic on the fp32 pipe. Error-free transforms via
// round-to-nearest intrinsics (never contracted by the compiler).
struct df { float h, l; };

__device__ __forceinline__ df df_make(double x) {
    float h = (float)x;
    float l = (float)(x - (double)h);
    df r; r.h = h; r.l = l; return r;
}
__device__ __forceinline__ double df_to_double(df x) {
    return (double)x.h + (double)x.l;
}
__device__ __forceinline__ df df_add(df a, df b) {
    float s  = __fadd_rn(a.h, b.h);
    float bb = __fsub_rn(s, a.h);
    float e  = __fadd_rn(__fsub_rn(a.h, __fsub_rn(s, bb)), __fsub_rn(b.h, bb));
    e = __fadd_rn(e, __fadd_rn(a.l, b.l));
    float s2 = __fadd_rn(s, e);
    float e2 = __fsub_rn(e, __fsub_rn(s2, s));
    df r; r.h = s2; r.l = e2; return r;
}
__device__ __forceinline__ df df_mul(df a, df b) {
    float p = __fmul_rn(a.h, b.h);
    float e = __fmaf_rn(a.h, b.h, -p);
    e = __fmaf_rn(a.h, b.l, e);
    e = __fmaf_rn(a.l, b.h, e);
    float s2 = __fadd_rn(p, e);
    float e2 = __fsub_rn(e, __fsub_rn(s2, p));
    df r; r.h = s2; r.l = e2; return r;
}
__device__ __forceinline__ df df_neg(df a) { df r; r.h = -a.h; r.l = -a.l; return r; }
__device__ __forceinline__ df df_sub(df a, df b) { return df_add(a, df_neg(b)); }
__device__ __forceinline__ df df_rcp(df d) {
    df iv; iv.h = __frcp_rn(d.h); iv.l = 0.f;
    df two; two.h = 2.0f; two.l = 0.f;
    #pragma unroll
    for (int it = 0; it < 2; it++) {
        df t = df_mul(d, iv);
        iv = df_mul(iv, df_sub(two, t));
    }
    return iv;
}

// ---------------------------------------------------------------------------
// Finalize via Schur-determinant LDL^T of the 54x54 bordered matrix
// BIG = [[pr_cov+aI, X^T],[X, la_cov+aI]]; rmi = sum_{k=27..53} log(sqrt(D_k)+1e-8).
// Hot loop in df64 on the fp32 pipe; fp64 only for fill + final logs.
__global__ __launch_bounds__(FT) void finalize_kernel(float* out) {
    __shared__ float2 A[BSZ*BSZ];
    __shared__ double red;
    int ch = blockIdx.x;
    int tid = threadIdx.x;
    const double* G = g_gram + (size_t)ch * GSZ * GSZ;
    const double invM = 1.0 / (double)(ND*ND*ND);   // 1/97336
    const double ALPHA = 0.0005;

    if (tid == 0) red = 0.0;

    // Fill lower triangle (fp64 mean-correction, then split to df64).
    // Index: a<27 -> pr_a (gram row 27+a), a>=27 -> la_{a-27} (gram row a-27).
    for (int e = tid; e < BSZ*BSZ; e += FT) {
        int a = e / BSZ, b = e % BSZ;
        if (b > a) continue;
        double v;
        if (a < 27) {               // pr-pr
            double Spa = G[54*GSZ + 27 + a], Spb = G[54*GSZ + 27 + b];
            v = G[(27+a)*GSZ + (27+b)] - Spa*Spb*invM + (a == b ? ALPHA : 0.0);
        } else if (b < 27) {        // la_{a-27} x pr_b
            int i = a - 27;
            double Sli = G[54*GSZ + i], Spb = G[54*GSZ + 27 + b];
            v = G[(27+b)*GSZ + i] - Sli*Spb*invM;
        } else {                    // la-la
            int i = a - 27, q = b - 27;   // i >= q
            double Sli = G[54*GSZ + i], Slq = G[54*GSZ + q];
            v = G[i*GSZ + q] - Sli*Slq*invM + (i == q ? ALPHA : 0.0);
        }
        df d = df_make(v);
        A[e] = make_float2(d.h, d.l);
    }
    __syncthreads();

    // fixed owner assignment of lower-triangle elements (i >= q)
    int iB[NPER], qB[NPER], qV[NPER];
    df accv[NPER];
    #pragma unroll
    for (int n = 0; n < NPER; n++) {
        int t = tid + n*FT;
        if (t < NTRI) {
            int i = (int)((sqrtf(8.0f*(float)t + 1.0f) - 1.0f) * 0.5f);
            while ((i+1)*(i+2)/2 <= t) i++;
            while (i*(i+1)/2 > t) i--;
            int q = t - i*(i+1)/2;
            iB[n] = i*BSZ; qB[n] = q*BSZ; qV[n] = q;
            float2 v = A[i*BSZ + q];
            accv[n].h = v.x; accv[n].l = v.y;
        } else {
            iB[n] = 0; qB[n] = 0; qV[n] = -1;
            accv[n].h = 0.f; accv[n].l = 0.f;
        }
    }

    // rank-1 LDL^T: A[i][q] -= A[i][k] * (A[q][k] * (1/D_k)),  q > k, i >= q
    for (int k = 0; k < BSZ - 1; k++) {
        float2 dv = A[k*BSZ + k];
        df D; D.h = dv.x; D.l = dv.y;
        df IV = df_rcp(D);            // redundant per lane, pure fp32
        #pragma unroll
        for (int n = 0; n < NPER; n++) {
            if (qV[n] > k) {
                float2 cik = A[iB[n] + k];
                float2 cqk = A[qB[n] + k];
                df Xik; Xik.h = cik.x; Xik.l = cik.y;
                df Xqk; Xqk.h = cqk.x; Xqk.l = cqk.y;
                df w = df_mul(Xik, df_mul(Xqk, IV));
                accv[n] = df_sub(accv[n], w);
                A[iB[n] + qV[n]] = make_float2(accv[n].h, accv[n].l);
            }
        }
        __syncthreads();
    }

    // pivots 27..53 are final; chol diag = sqrt(D_k)
    if (tid >= 27 && tid < 54) {
        float2 dv = A[tid*BSZ + tid];
        double d = (double)dv.x + (double)dv.y;
        atomicAdd(&red, log(sqrt(d) + 1e-8));
    }
    __syncthreads();
    if (tid == 0) atomicAdd(out, (float)(red / 54.0));
}

// ---------------------------------------------------------------------------
extern "C" void kernel_launch(void* const* d_in, const int* in_sizes, int n_in,
                              void* d_out, int out_size) {
    const float* logits = (const float*)d_in[0];
    const int*   labels = (const int*)d_in[1];
    float* out = (float*)d_out;

    cudaFuncSetAttribute(gram_kernel,
                         cudaFuncAttributeMaxDynamicSharedMemorySize,
                         SMEMF * (int)sizeof(float));

    zero_kernel<<<(NCH*GSZ*GSZ + 255)/256, 256>>>(out);
    pool_kernel<<<(NCH*PVOL + 255)/256, 256>>>(logits, labels);
    dim3 g(32, NCH);   // 32 spatial pairs x 8 channels = 256 blocks
    gram_kernel<<<g, 64, SMEMF * sizeof(float)>>>();
    finalize_kernel<<<NCH, FT>>>(out);
}

// round 10
// speedup vs baseline: 2.2411x; 1.2293x over previous
#include <cuda_runtime.h>
#include <math.h>

#define NCH 8            // 2 batches x 4 classes
#define GD 96            // input spatial dim
#define PD 48            // pooled dim
#define PVOL (PD*PD*PD)  // 110592
#define ND 46            // base-voxel dim (48 - 2)
#define GSZ 64           // padded gram row stride (rows/cols 0..54 used)

#define BY 6             // y tile edge
#define BZ 2             // z slab (base voxels per block)
#define RXP 50           // padded raw tile x-extent
#define RY 8             // BY + 2 halo
#define RZ 4             // BZ + 2 halo
#define REG (RZ*RY*RXP)  // 1600 floats per region (used part)
#define REGP 1608        // region stride
#define OFF_ONES (4*REGP)
#define SMEMF (5*REGP)   // floats of dynamic smem (~32KB)

#define FT 256           // finalize threads
#define BSZ 54           // big matrix size
#define NTRI (BSZ*(BSZ+1)/2)   // 1485 lower-tri elements
#define NPER 6                 // ceil(1485/256)

static __device__ float  g_la[NCH*PVOL];
static __device__ float  g_pr[NCH*PVOL];
static __device__ double g_gram[NCH*GSZ*GSZ];

// ---------------------------------------------------------------------------
__global__ void zero_kernel(float* out) {
    int i = blockIdx.x * blockDim.x + threadIdx.x;
    if (i < NCH*GSZ*GSZ) g_gram[i] = 0.0;
    if (i == 0) out[0] = 0.0f;
}

// ---------------------------------------------------------------------------
__global__ void pool_kernel(const float* __restrict__ logits,
                            const int* __restrict__ labels) {
    int idx = blockIdx.x * blockDim.x + threadIdx.x;
    if (idx >= NCH*PVOL) return;
    int ch  = idx / PVOL;
    int rem = idx - ch * PVOL;
    int p0 = rem / (PD*PD);
    int p1 = (rem / PD) % PD;
    int p2 = rem % PD;
    int n = ch >> 2;
    int c = ch & 3;

    const float* lg = logits + (size_t)ch * GD*GD*GD;
    const int*   lb = labels + (size_t)n  * GD*GD*GD;

    float la = 0.f, pr = 0.f;
    #pragma unroll
    for (int d0 = 0; d0 < 2; d0++) {
        #pragma unroll
        for (int d1 = 0; d1 < 2; d1++) {
            int base = ((2*p0 + d0) * GD + (2*p1 + d1)) * GD + 2*p2;
            float2 lv = *reinterpret_cast<const float2*>(lg + base);
            int2   bv = *reinterpret_cast<const int2*>(lb + base);
            {
                bool m = (bv.x < 4);
                if (m && bv.x == c) la = 1.f;
                float s = 1.f / (1.f + expf(-lv.x));
                float p = (m ? s : 0.f) + 1e-6f;
                pr = fmaxf(pr, p);
            }
            {
                bool m = (bv.y < 4);
                if (m && bv.y == c) la = 1.f;
                float s = 1.f / (1.f + expf(-lv.y));
                float p = (m ? s : 0.f) + 1e-6f;
                pr = fmaxf(pr, p);
            }
        }
    }
    g_la[idx] = la;
    g_pr[idx] = pr;
}

// ---------------------------------------------------------------------------
// Gram: triangular 7x7 tile grid (28 jobs per spatial tile), two y-adjacent
// spatial tiles per 64-thread block, z split into 2-voxel slabs for occupancy.
__device__ __forceinline__ int dof(int r, int laOff) {
    if (r < 27)  return laOff + ((r/9)*RY + (r/3)%3) * RXP + (r%3);
    if (r < 54) { int q = r - 27; return laOff + REGP + ((q/9)*RY + (q/3)%3) * RXP + (q%3); }
    return OFF_ONES;
}

__global__ __launch_bounds__(64) void gram_kernel() {
    extern __shared__ float s[];
    int ch    = blockIdx.z;
    int ypair = blockIdx.x;        // 0..3
    int zslab = blockIdx.y;        // 0..22
    int y0A = ypair * (2*BY);
    int y0B = y0A + BY;
    int z0  = zslab * BZ;          // base z, 0..44
    int tid = threadIdx.x;

    const float* la = g_la + (size_t)ch * PVOL;
    const float* pr = g_pr + (size_t)ch * PVOL;

    // load 4-z-row halo regions for tiles A and B, plus ones region
    for (int i = tid; i < REG; i += 64) {
        int x = i % RXP;
        int t = i / RXP;
        int y = t % RY, z = t / RY;     // z in [0,4)
        int gz = z0 + z;                // <= 44+3 = 47 < 48
        float laA = 0.f, prA = 0.f, laB = 0.f, prB = 0.f;
        if (x < PD) {
            int gyA = y0A + y, gyB = y0B + y;
            if (gyA < PD) { int gi = (gz*PD + gyA)*PD + x; laA = la[gi]; prA = pr[gi]; }
            if (gyB < PD) { int gi = (gz*PD + gyB)*PD + x; laB = la[gi]; prB = pr[gi]; }
        }
        s[i]           = laA;
        s[REGP + i]    = prA;
        s[2*REGP + i]  = laB;
        s[3*REGP + i]  = prB;
        s[OFF_ONES + i] = 1.0f;
    }
    __syncthreads();

    bool active = (tid < 56);
    bool isB = (tid >= 28) && (tid < 56);
    int j = active ? (isB ? tid - 28 : tid) : 0;
    int R = 0, jj = j;
    while (jj >= R + 1) { jj -= R + 1; R++; }
    int C = jj;                      // lower-triangle tile (R>=C) in 7x7 grid

    int laOff = isB ? 2*REGP : 0;
    int myY0  = isB ? y0B : y0A;
    int myYC  = min(BY, ND - myY0);
    int zC    = min(BZ, ND - z0);    // always 2

    int rdel[8], cdel[8];
    #pragma unroll
    for (int i = 0; i < 8; i++) {
        rdel[i] = dof(R*8 + i, laOff);
        cdel[i] = dof(C*8 + i, laOff);
    }

    float acc[8][8];
    #pragma unroll
    for (int i = 0; i < 8; i++)
        #pragma unroll
        for (int q = 0; q < 8; q++) acc[i][q] = 0.f;

    for (int zb = 0; zb < zC; zb++) {
        for (int yb = 0; yb < BY; yb++) {
            if (yb >= myYC) continue;
            int kb = (zb*RY + yb) * RXP;
            #pragma unroll 2
            for (int xb = 0; xb < ND; xb++) {
                int k = kb + xb;
                float a[8], b[8];
                #pragma unroll
                for (int i = 0; i < 8; i++) a[i] = s[rdel[i] + k];
                #pragma unroll
                for (int q = 0; q < 8; q++) b[q] = s[cdel[q] + k];
                #pragma unroll
                for (int i = 0; i < 8; i++)
                    #pragma unroll
                    for (int q = 0; q < 8; q++)
                        acc[i][q] = fmaf(a[i], b[q], acc[i][q]);
            }
        }
    }

    if (active) {
        double* G = g_gram + (size_t)ch * GSZ * GSZ;
        #pragma unroll
        for (int i = 0; i < 8; i++) {
            int r = R*8 + i;
            if (r > 54) continue;
            #pragma unroll
            for (int q = 0; q < 8; q++) {
                int c = C*8 + q;
                if (c > 54) continue;
                if (R == C && q > i) continue;
                atomicAdd(&G[r*GSZ + c], (double)acc[i][q]);
            }
        }
    }
}

// ---------------------------------------------------------------------------
// double-float (df64) arithmetic on the fp32 pipe.
struct df { float h, l; };

__device__ __forceinline__ df df_make(double x) {
    float h = (float)x;
    float l = (float)(x - (double)h);
    df r; r.h = h; r.l = l; return r;
}
__device__ __forceinline__ df df_add(df a, df b) {
    float s  = __fadd_rn(a.h, b.h);
    float bb = __fsub_rn(s, a.h);
    float e  = __fadd_rn(__fsub_rn(a.h, __fsub_rn(s, bb)), __fsub_rn(b.h, bb));
    e = __fadd_rn(e, __fadd_rn(a.l, b.l));
    float s2 = __fadd_rn(s, e);
    float e2 = __fsub_rn(e, __fsub_rn(s2, s));
    df r; r.h = s2; r.l = e2; return r;
}
__device__ __forceinline__ df df_mul(df a, df b) {
    float p = __fmul_rn(a.h, b.h);
    float e = __fmaf_rn(a.h, b.h, -p);
    e = __fmaf_rn(a.h, b.l, e);
    e = __fmaf_rn(a.l, b.h, e);
    float s2 = __fadd_rn(p, e);
    float e2 = __fsub_rn(e, __fsub_rn(s2, p));
    df r; r.h = s2; r.l = e2; return r;
}
__device__ __forceinline__ df df_neg(df a) { df r; r.h = -a.h; r.l = -a.l; return r; }
__device__ __forceinline__ df df_sub(df a, df b) { return df_add(a, df_neg(b)); }
__device__ __forceinline__ df df_rcp(df d) {
    df iv; iv.h = __frcp_rn(d.h); iv.l = 0.f;
    df two; two.h = 2.0f; two.l = 0.f;
    #pragma unroll
    for (int it = 0; it < 2; it++) {
        df t = df_mul(d, iv);
        iv = df_mul(iv, df_sub(two, t));
    }
    return iv;
}

// ---------------------------------------------------------------------------
// Finalize via Schur-determinant LDL^T of the 54x54 bordered matrix.
// df64 hot loop on the fp32 pipe; 256 threads (2 warps/SMSP) for issue rate.
__global__ __launch_bounds__(FT) void finalize_kernel(float* out) {
    __shared__ float2 A[BSZ*BSZ];
    __shared__ double red;
    int ch = blockIdx.x;
    int tid = threadIdx.x;
    const double* G = g_gram + (size_t)ch * GSZ * GSZ;
    const double invM = 1.0 / (double)(ND*ND*ND);   // 1/97336
    const double ALPHA = 0.0005;

    if (tid == 0) red = 0.0;

    for (int e = tid; e < BSZ*BSZ; e += FT) {
        int a = e / BSZ, b = e % BSZ;
        if (b > a) continue;
        double v;
        if (a < 27) {               // pr-pr
            double Spa = G[54*GSZ + 27 + a], Spb = G[54*GSZ + 27 + b];
            v = G[(27+a)*GSZ + (27+b)] - Spa*Spb*invM + (a == b ? ALPHA : 0.0);
        } else if (b < 27) {        // la_{a-27} x pr_b
            int i = a - 27;
            double Sli = G[54*GSZ + i], Spb = G[54*GSZ + 27 + b];
            v = G[(27+b)*GSZ + i] - Sli*Spb*invM;
        } else {                    // la-la
            int i = a - 27, q = b - 27;   // i >= q
            double Sli = G[54*GSZ + i], Slq = G[54*GSZ + q];
            v = G[i*GSZ + q] - Sli*Slq*invM + (i == q ? ALPHA : 0.0);
        }
        df d = df_make(v);
        A[e] = make_float2(d.h, d.l);
    }
    __syncthreads();

    int iB[NPER], qB[NPER], qV[NPER];
    df accv[NPER];
    #pragma unroll
    for (int n = 0; n < NPER; n++) {
        int t = tid + n*FT;
        if (t < NTRI) {
            int i = (int)((sqrtf(8.0f*(float)t + 1.0f) - 1.0f) * 0.5f);
            while ((i+1)*(i+2)/2 <= t) i++;
            while (i*(i+1)/2 > t) i--;
            int q = t - i*(i+1)/2;
            iB[n] = i*BSZ; qB[n] = q*BSZ; qV[n] = q;
            float2 v = A[i*BSZ + q];
            accv[n].h = v.x; accv[n].l = v.y;
        } else {
            iB[n] = 0; qB[n] = 0; qV[n] = -1;
            accv[n].h = 0.f; accv[n].l = 0.f;
        }
    }

    for (int k = 0; k < BSZ - 1; k++) {
        float2 dv = A[k*BSZ + k];
        df D; D.h = dv.x; D.l = dv.y;
        df IV = df_rcp(D);
        #pragma unroll
        for (int n = 0; n < NPER; n++) {
            if (qV[n] > k) {
                float2 cik = A[iB[n] + k];
                float2 cqk = A[qB[n] + k];
                df Xik; Xik.h = cik.x; Xik.l = cik.y;
                df Xqk; Xqk.h = cqk.x; Xqk.l = cqk.y;
                df w = df_mul(Xik, df_mul(Xqk, IV));
                accv[n] = df_sub(accv[n], w);
                A[iB[n] + qV[n]] = make_float2(accv[n].h, accv[n].l);
            }
        }
        __syncthreads();
    }

    if (tid >= 27 && tid < 54) {
        float2 dv = A[tid*BSZ + tid];
        double d = (double)dv.x + (double)dv.y;
        atomicAdd(&red, log(sqrt(d) + 1e-8));
    }
    __syncthreads();
    if (tid == 0) atomicAdd(out, (float)(red / 54.0));
}

// ---------------------------------------------------------------------------
extern "C" void kernel_launch(void* const* d_in, const int* in_sizes, int n_in,
                              void* d_out, int out_size) {
    const float* logits = (const float*)d_in[0];
    const int*   labels = (const int*)d_in[1];
    float* out = (float*)d_out;

    cudaFuncSetAttribute(gram_kernel,
                         cudaFuncAttributeMaxDynamicSharedMemorySize,
                         SMEMF * (int)sizeof(float));

    zero_kernel<<<(NCH*GSZ*GSZ + 255)/256, 256>>>(out);
    pool_kernel<<<(NCH*PVOL + 255)/256, 256>>>(logits, labels);
    dim3 g(4, 23, NCH);   // 4 y-pairs x 23 z-slabs x 8 channels = 736 blocks
    gram_kernel<<<g, 64, SMEMF * sizeof(float)>>>();
    finalize_kernel<<<NCH, FT>>>(out);
}

// round 11
// speedup vs baseline: 2.3812x; 1.0625x over previous
#include <cuda_runtime.h>
#include <math.h>

#define NCH 8            // 2 batches x 4 classes
#define GD 96            // input spatial dim
#define PD 48            // pooled dim
#define PVOL (PD*PD*PD)  // 110592
#define ND 46            // base-voxel dim (48 - 2)
#define GSZ 64           // padded gram row stride (rows/cols 0..54 used)

#define BY 6             // y tile edge
#define BZ 2             // z slab (base voxels per block)
#define RXP 50           // padded raw tile x-extent
#define RY 8             // BY + 2 halo
#define RZ 4             // BZ + 2 halo
#define REG (RZ*RY*RXP)  // 1600 floats per region (used part)
#define REGP 1608        // region stride
#define OFF_ONES (4*REGP)
#define SMEMF (5*REGP)   // floats of dynamic smem (~32KB)

#define FT 512           // finalize threads
#define BSZ 54           // big matrix size
#define NTRI (BSZ*(BSZ+1)/2)   // 1485 lower-tri elements
#define NPER 3                 // ceil(1485/512)

static __device__ float  g_la[NCH*PVOL];
static __device__ float  g_pr[NCH*PVOL];
static __device__ double g_gram[NCH*GSZ*GSZ];

// packed f32x2 helpers -------------------------------------------------------
#define PACK2(out, lo, hi) \
    asm("mov.b64 %0, {%1, %2};" : "=l"(out) : "r"(lo), "r"(hi))
#define UNPACK2(lo, hi, in) \
    asm("mov.b64 {%0, %1}, %2;" : "=r"(lo), "=r"(hi) : "l"(in))
#define FMA_F32X2(d, a, b) \
    asm("fma.rn.f32x2 %0, %1, %2, %0;" : "+l"(d) : "l"(a), "l"(b))

// ---------------------------------------------------------------------------
// Pool: sigmoid+mask / one-hot + 2x2x2 max-pool; also zeroes g_gram and out.
__global__ void pool_kernel(const float* __restrict__ logits,
                            const int* __restrict__ labels, float* out) {
    int idx = blockIdx.x * blockDim.x + threadIdx.x;
    if (idx < NCH*GSZ*GSZ) g_gram[idx] = 0.0;
    if (idx == 0) out[0] = 0.0f;
    if (idx >= NCH*PVOL) return;
    int ch  = idx / PVOL;
    int rem = idx - ch * PVOL;
    int p0 = rem / (PD*PD);
    int p1 = (rem / PD) % PD;
    int p2 = rem % PD;
    int n = ch >> 2;
    int c = ch & 3;

    const float* lg = logits + (size_t)ch * GD*GD*GD;
    const int*   lb = labels + (size_t)n  * GD*GD*GD;

    float la = 0.f, pr = 0.f;
    #pragma unroll
    for (int d0 = 0; d0 < 2; d0++) {
        #pragma unroll
        for (int d1 = 0; d1 < 2; d1++) {
            int base = ((2*p0 + d0) * GD + (2*p1 + d1)) * GD + 2*p2;
            float2 lv = *reinterpret_cast<const float2*>(lg + base);
            int2   bv = *reinterpret_cast<const int2*>(lb + base);
            {
                bool m = (bv.x < 4);
                if (m && bv.x == c) la = 1.f;
                float s = 1.f / (1.f + expf(-lv.x));
                float p = (m ? s : 0.f) + 1e-6f;
                pr = fmaxf(pr, p);
            }
            {
                bool m = (bv.y < 4);
                if (m && bv.y == c) la = 1.f;
                float s = 1.f / (1.f + expf(-lv.y));
                float p = (m ? s : 0.f) + 1e-6f;
                pr = fmaxf(pr, p);
            }
        }
    }
    g_la[idx] = la;
    g_pr[idx] = pr;
}

// ---------------------------------------------------------------------------
// Gram: triangular 7x7 tile grid, two y-adjacent spatial tiles per block,
// 2-voxel z slabs; inner loop on fma.rn.f32x2 (packed pairs of columns).
__device__ __forceinline__ int dof(int r, int laOff) {
    if (r < 27)  return laOff + ((r/9)*RY + (r/3)%3) * RXP + (r%3);
    if (r < 54) { int q = r - 27; return laOff + REGP + ((q/9)*RY + (q/3)%3) * RXP + (q%3); }
    return OFF_ONES;
}

__global__ __launch_bounds__(64) void gram_kernel() {
    extern __shared__ float s[];
    int ch    = blockIdx.z;
    int ypair = blockIdx.x;        // 0..3
    int zslab = blockIdx.y;        // 0..22
    int y0A = ypair * (2*BY);
    int y0B = y0A + BY;
    int z0  = zslab * BZ;
    int tid = threadIdx.x;

    const float* la = g_la + (size_t)ch * PVOL;
    const float* pr = g_pr + (size_t)ch * PVOL;

    for (int i = tid; i < REG; i += 64) {
        int x = i % RXP;
        int t = i / RXP;
        int y = t % RY, z = t / RY;
        int gz = z0 + z;
        float laA = 0.f, prA = 0.f, laB = 0.f, prB = 0.f;
        if (x < PD) {
            int gyA = y0A + y, gyB = y0B + y;
            if (gyA < PD) { int gi = (gz*PD + gyA)*PD + x; laA = la[gi]; prA = pr[gi]; }
            if (gyB < PD) { int gi = (gz*PD + gyB)*PD + x; laB = la[gi]; prB = pr[gi]; }
        }
        s[i]           = laA;
        s[REGP + i]    = prA;
        s[2*REGP + i]  = laB;
        s[3*REGP + i]  = prB;
        s[OFF_ONES + i] = 1.0f;
    }
    __syncthreads();

    bool active = (tid < 56);
    bool isB = (tid >= 28) && (tid < 56);
    int j = active ? (isB ? tid - 28 : tid) : 0;
    int R = 0, jj = j;
    while (jj >= R + 1) { jj -= R + 1; R++; }
    int C = jj;                      // lower-triangle tile (R>=C) in 7x7 grid

    int laOff = isB ? 2*REGP : 0;
    int myY0  = isB ? y0B : y0A;
    int myYC  = min(BY, ND - myY0);
    int zC    = min(BZ, ND - z0);

    int rdel[8], cdel[8];
    #pragma unroll
    for (int i = 0; i < 8; i++) {
        rdel[i] = dof(R*8 + i, laOff);
        cdel[i] = dof(C*8 + i, laOff);
    }

    unsigned long long acc2[8][4];
    #pragma unroll
    for (int i = 0; i < 8; i++)
        #pragma unroll
        for (int q = 0; q < 4; q++) acc2[i][q] = 0ULL;

    for (int zb = 0; zb < zC; zb++) {
        for (int yb = 0; yb < BY; yb++) {
            if (yb >= myYC) continue;
            int kb = (zb*RY + yb) * RXP;
            #pragma unroll 2
            for (int xb = 0; xb < ND; xb++) {
                int k = kb + xb;
                float a[8], b[8];
                #pragma unroll
                for (int i = 0; i < 8; i++) a[i] = s[rdel[i] + k];
                #pragma unroll
                for (int q = 0; q < 8; q++) b[q] = s[cdel[q] + k];
                unsigned long long b2[4];
                #pragma unroll
                for (int q = 0; q < 4; q++)
                    PACK2(b2[q], __float_as_uint(b[2*q]), __float_as_uint(b[2*q+1]));
                #pragma unroll
                for (int i = 0; i < 8; i++) {
                    unsigned long long a2;
                    PACK2(a2, __float_as_uint(a[i]), __float_as_uint(a[i]));
                    #pragma unroll
                    for (int q = 0; q < 4; q++)
                        FMA_F32X2(acc2[i][q], a2, b2[q]);
                }
            }
        }
    }

    if (active) {
        double* G = g_gram + (size_t)ch * GSZ * GSZ;
        #pragma unroll
        for (int i = 0; i < 8; i++) {
            int r = R*8 + i;
            if (r > 54) continue;
            #pragma unroll
            for (int q = 0; q < 4; q++) {
                unsigned int lo, hi;
                UNPACK2(lo, hi, acc2[i][q]);
                int c0 = C*8 + 2*q;
                if (c0 <= r && !(R == C && 2*q > i))
                    atomicAdd(&G[r*GSZ + c0], (double)__uint_as_float(lo));
                if (c0 + 1 <= r && !(R == C && 2*q + 1 > i))
                    atomicAdd(&G[r*GSZ + c0 + 1], (double)__uint_as_float(hi));
            }
        }
    }
}

// ---------------------------------------------------------------------------
// double-float (df64) arithmetic on the fp32 pipe.
struct df { float h, l; };

__device__ __forceinline__ df df_make(double x) {
    float h = (float)x;
    float l = (float)(x - (double)h);
    df r; r.h = h; r.l = l; return r;
}
__device__ __forceinline__ df df_add(df a, df b) {
    float s  = __fadd_rn(a.h, b.h);
    float bb = __fsub_rn(s, a.h);
    float e  = __fadd_rn(__fsub_rn(a.h, __fsub_rn(s, bb)), __fsub_rn(b.h, bb));
    e = __fadd_rn(e, __fadd_rn(a.l, b.l));
    float s2 = __fadd_rn(s, e);
    float e2 = __fsub_rn(e, __fsub_rn(s2, s));
    df r; r.h = s2; r.l = e2; return r;
}
__device__ __forceinline__ df df_mul(df a, df b) {
    float p = __fmul_rn(a.h, b.h);
    float e = __fmaf_rn(a.h, b.h, -p);
    e = __fmaf_rn(a.h, b.l, e);
    e = __fmaf_rn(a.l, b.h, e);
    float s2 = __fadd_rn(p, e);
    float e2 = __fsub_rn(e, __fsub_rn(s2, p));
    df r; r.h = s2; r.l = e2; return r;
}
__device__ __forceinline__ df df_neg(df a) { df r; r.h = -a.h; r.l = -a.l; return r; }
__device__ __forceinline__ df df_sub(df a, df b) { return df_add(a, df_neg(b)); }
__device__ __forceinline__ df df_rcp(df d) {
    df iv; iv.h = __frcp_rn(d.h); iv.l = 0.f;
    df two; two.h = 2.0f; two.l = 0.f;
    #pragma unroll
    for (int it = 0; it < 2; it++) {
        df t = df_mul(d, iv);
        iv = df_mul(iv, df_sub(two, t));
    }
    return iv;
}

// ---------------------------------------------------------------------------
// Finalize via Schur-determinant LDL^T of the 54x54 bordered matrix.
__global__ __launch_bounds__(FT) void finalize_kernel(float* out) {
    __shared__ float2 A[BSZ*BSZ];
    __shared__ double red;
    int ch = blockIdx.x;
    int tid = threadIdx.x;
    const double* G = g_gram + (size_t)ch * GSZ * GSZ;
    const double invM = 1.0 / (double)(ND*ND*ND);   // 1/97336
    const double ALPHA = 0.0005;

    if (tid == 0) red = 0.0;

    for (int e = tid; e < BSZ*BSZ; e += FT) {
        int a = e / BSZ, b = e % BSZ;
        if (b > a) continue;
        double v;
        if (a < 27) {               // pr-pr
            double Spa = G[54*GSZ + 27 + a], Spb = G[54*GSZ + 27 + b];
            v = G[(27+a)*GSZ + (27+b)] - Spa*Spb*invM + (a == b ? ALPHA : 0.0);
        } else if (b < 27) {        // la_{a-27} x pr_b
            int i = a - 27;
            double Sli = G[54*GSZ + i], Spb = G[54*GSZ + 27 + b];
            v = G[(27+b)*GSZ + i] - Sli*Spb*invM;
        } else {                    // la-la
            int i = a - 27, q = b - 27;   // i >= q
            double Sli = G[54*GSZ + i], Slq = G[54*GSZ + q];
            v = G[i*GSZ + q] - Sli*Slq*invM + (i == q ? ALPHA : 0.0);
        }
        df d = df_make(v);
        A[e] = make_float2(d.h, d.l);
    }
    __syncthreads();

    int iB[NPER], qB[NPER], qV[NPER];
    df accv[NPER];
    #pragma unroll
    for (int n = 0; n < NPER; n++) {
        int t = tid + n*FT;
        if (t < NTRI) {
            int i = (int)((sqrtf(8.0f*(float)t + 1.0f) - 1.0f) * 0.5f);
            while ((i+1)*(i+2)/2 <= t) i++;
            while (i*(i+1)/2 > t) i--;
            int q = t - i*(i+1)/2;
            iB[n] = i*BSZ; qB[n] = q*BSZ; qV[n] = q;
            float2 v = A[i*BSZ + q];
            accv[n].h = v.x; accv[n].l = v.y;
        } else {
            iB[n] = 0; qB[n] = 0; qV[n] = -1;
            accv[n].h = 0.f; accv[n].l = 0.f;
        }
    }

    for (int k = 0; k < BSZ - 1; k++) {
        float2 dv = A[k*BSZ + k];
        df D; D.h = dv.x; D.l = dv.y;
        df IV = df_rcp(D);
        #pragma unroll
        for (int n = 0; n < NPER; n++) {
            if (qV[n] > k) {
                float2 cik = A[iB[n] + k];
                float2 cqk = A[qB[n] + k];
                df Xik; Xik.h = cik.x; Xik.l = cik.y;
                df Xqk; Xqk.h = cqk.x; Xqk.l = cqk.y;
                df w = df_mul(Xik, df_mul(Xqk, IV));
                accv[n] = df_sub(accv[n], w);
                A[iB[n] + qV[n]] = make_float2(accv[n].h, accv[n].l);
            }
        }
        __syncthreads();
    }

    if (tid >= 27 && tid < 54) {
        float2 dv = A[tid*BSZ + tid];
        double d = (double)dv.x + (double)dv.y;
        atomicAdd(&red, log(sqrt(d) + 1e-8));
    }
    __syncthreads();
    if (tid == 0) atomicAdd(out, (float)(red / 54.0));
}

// ---------------------------------------------------------------------------
extern "C" void kernel_launch(void* const* d_in, const int* in_sizes, int n_in,
                              void* d_out, int out_size) {
    const float* logits = (const float*)d_in[0];
    const int*   labels = (const int*)d_in[1];
    float* out = (float*)d_out;

    cudaFuncSetAttribute(gram_kernel,
                         cudaFuncAttributeMaxDynamicSharedMemorySize,
                         SMEMF * (int)sizeof(float));

    pool_kernel<<<(NCH*PVOL + 255)/256, 256>>>(logits, labels, out);
    dim3 g(4, 23, NCH);   // 4 y-pairs x 23 z-slabs x 8 channels = 736 blocks
    gram_kernel<<<g, 64, SMEMF * sizeof(float)>>>();
    finalize_kernel<<<NCH, FT>>>(out);
}